// round 6
// baseline (speedup 1.0000x reference)
#include <cuda_runtime.h>
#include <math.h>
#include <cstdint>

#define NUM_E   8
#define BATCH   4
#define CCAP    1024
#define DMODEL  1024
#define DFF     4096

// CTA tile 128x256, BK=32; 8 warps in 2x4 grid, each warp 64x64.
#define BM 128
#define BN 256
#define BK 32

// Row-major smem tiles, 32 words (128B) per row, XOR-swizzled chunks:
//   chunk' = chunk ^ (row & 7), chunk = 16B unit within the row.
#define A_TILE_BYTES (BM * BK * 4)                    // 16384
#define B_TILE_BYTES (BN * BK * 4)                    // 32768
#define STAGE_BYTES  (A_TILE_BYTES + B_TILE_BYTES)    // 49152
#define SMEM_BYTES   (2 * STAGE_BYTES + 128)

// 512 MB fp32 scratch for h = gelu(x@W1^T + b1)
__device__ float g_h[134217728];

__device__ __forceinline__ uint32_t smem_u32(const void* p) {
    uint32_t a;
    asm("{ .reg .u64 t; cvta.to.shared.u64 t, %1; cvt.u32.u64 %0, t; }" : "=r"(a) : "l"(p));
    return a;
}
__device__ __forceinline__ unsigned f2tf32(float x) {
    unsigned y;
    asm("cvt.rna.tf32.f32 %0, %1;" : "=r"(y) : "f"(x));
    return y;
}
__device__ __forceinline__ void sts128(uint32_t addr, uint4 v) {
    asm volatile("st.shared.v4.b32 [%0], {%1,%2,%3,%4};"
                 :: "r"(addr), "r"(v.x), "r"(v.y), "r"(v.z), "r"(v.w) : "memory");
}
__device__ __forceinline__ void ldsm_x4(unsigned r[4], uint32_t a) {
    asm volatile("ldmatrix.sync.aligned.m8n8.x4.shared.b16 {%0,%1,%2,%3}, [%4];"
                 : "=r"(r[0]), "=r"(r[1]), "=r"(r[2]), "=r"(r[3]) : "r"(a));
}
__device__ __forceinline__ void ldsm_x2(unsigned r[2], uint32_t a) {
    asm volatile("ldmatrix.sync.aligned.m8n8.x2.shared.b16 {%0,%1}, [%2];"
                 : "=r"(r[0]), "=r"(r[1]) : "r"(a));
}
__device__ __forceinline__ void mma_tf32(float acc[4], const unsigned a[4], const unsigned b[2]) {
    asm volatile(
        "mma.sync.aligned.m16n8k8.row.col.f32.tf32.tf32.f32 "
        "{%0,%1,%2,%3}, {%4,%5,%6,%7}, {%8,%9}, {%0,%1,%2,%3};\n"
        : "+f"(acc[0]), "+f"(acc[1]), "+f"(acc[2]), "+f"(acc[3])
        : "r"(a[0]), "r"(a[1]), "r"(a[2]), "r"(a[3]),
          "r"(b[0]), "r"(b[1]));
}
__device__ __forceinline__ float gelu_exact(float x) {
    return 0.5f * x * (1.0f + erff(x * 0.7071067811865476f));
}

// Grouped NT GEMM: O[grp][m][n] = sum_k A[grp][m][k] * W[e][n][k] + bias[e][n] (opt gelu)
template<int NTOT, int KTOT, bool GELU>
__global__ void __launch_bounds__(256, 1)
grouped_ffn(const float* __restrict__ A0, const float* __restrict__ W0,
            const float* __restrict__ bias0, float* __restrict__ O0)
{
    extern __shared__ char smraw[];
    const uint32_t sm32 = (smem_u32(smraw) + 127u) & ~127u;

    const int tid  = threadIdx.x;
    const int wid  = tid >> 5;
    const int lane = tid & 31;
    const int wr   = wid >> 2;    // 0..1  (64-row slab)
    const int wc   = wid & 3;     // 0..3  (64-col slab)
    const int g    = lane >> 2;   // 0..7
    const int tq   = lane & 3;    // 0..3

    const int grp = blockIdx.z;
    const int e   = grp & (NUM_E - 1);
    const int bm  = blockIdx.y * BM;
    const int bn  = blockIdx.x * BN;

    const float* A = A0 + (size_t)grp * CCAP * KTOT + (size_t)bm * KTOT;
    const float* W = W0 + (size_t)e * NTOT * KTOT + (size_t)bn * KTOT;

    // ---- writer plan: thread t -> row (t>>3)+32i, 16B chunk (t&7) ----
    const int wrow = tid >> 3;    // 0..31
    const int wchk = tid & 7;     // 0..7
    const float* Ag = A + (size_t)wrow * KTOT + wchk * 4;
    const float* Wg = W + (size_t)wrow * KTOT + wchk * 4;

    // swizzled STS byte offsets within a tile (row&7 invariant under +32)
    uint32_t aso[4], bso[8];
    {
        const uint32_t sc = (uint32_t)(wchk ^ (wrow & 7)) << 4;
        #pragma unroll
        for (int i = 0; i < 4; ++i) aso[i] = (uint32_t)(wrow + 32 * i) * 128 + sc;
        #pragma unroll
        for (int i = 0; i < 8; ++i) bso[i] = (uint32_t)(wrow + 32 * i) * 128 + sc;
    }

    float4 ra[4], rb[8];
    auto LDG_TILE = [&](int kt) {
        const size_t k0 = (size_t)kt * BK;
        #pragma unroll
        for (int i = 0; i < 4; ++i)
            ra[i] = *reinterpret_cast<const float4*>(Ag + (size_t)(i * 32) * KTOT + k0);
        #pragma unroll
        for (int i = 0; i < 8; ++i)
            rb[i] = *reinterpret_cast<const float4*>(Wg + (size_t)(i * 32) * KTOT + k0);
    };
    auto STS_A = [&](int d) {
        const uint32_t base = sm32 + d * STAGE_BYTES;
        #pragma unroll
        for (int i = 0; i < 4; ++i)
            sts128(base + aso[i],
                   make_uint4(f2tf32(ra[i].x), f2tf32(ra[i].y), f2tf32(ra[i].z), f2tf32(ra[i].w)));
    };
    auto STS_B = [&](int d) {
        const uint32_t base = sm32 + d * STAGE_BYTES + A_TILE_BYTES;
        #pragma unroll
        for (int i = 0; i < 8; ++i)
            sts128(base + bso[i],
                   make_uint4(f2tf32(rb[i].x), f2tf32(rb[i].y), f2tf32(rb[i].z), f2tf32(rb[i].w)));
    };

    // ---- ldmatrix consumer plan ----
    const uint32_t lo7 = lane & 7;
    const uint32_t ahi = (lane >> 4) & 1;   // A: +1 chunk for 2nd k-half tiles
    const uint32_t arw = (lane >> 3) & 1;   // A: +8 rows for tiles 1,3
    const uint32_t bhi = (lane >> 3) & 1;   // B: +1 chunk for tile 1
    // per-kb swizzled chunk byte offsets
    uint32_t axo[4], bxo[4];
    #pragma unroll
    for (int kb = 0; kb < 4; ++kb) {
        axo[kb] = (((2u * kb + ahi) ^ lo7) << 4);
        bxo[kb] = (((2u * kb + bhi) ^ lo7) << 4);
    }
    const uint32_t aRow = (uint32_t)(wr * 64 + lo7 + 8 * arw) * 128;  // + mi*2048
    const uint32_t bRow = (uint32_t)(wc * 64 + lo7) * 128;            // + ni*1024

    float acc[4][8][4];
    #pragma unroll
    for (int mi = 0; mi < 4; ++mi)
        #pragma unroll
        for (int ni = 0; ni < 8; ++ni)
            #pragma unroll
            for (int c = 0; c < 4; ++c)
                acc[mi][ni][c] = 0.0f;

    auto COMPUTE_KB = [&](uint32_t sbase, int kb) {
        unsigned af[4][4], bf[8][2];
        #pragma unroll
        for (int mi = 0; mi < 4; ++mi)
            ldsm_x4(af[mi], sbase + aRow + mi * 2048 + axo[kb]);
        #pragma unroll
        for (int ni = 0; ni < 8; ++ni)
            ldsm_x2(bf[ni], sbase + A_TILE_BYTES + bRow + ni * 1024 + bxo[kb]);
        #pragma unroll
        for (int mi = 0; mi < 4; ++mi)
            #pragma unroll
            for (int ni = 0; ni < 8; ++ni)
                mma_tf32(acc[mi][ni], af[mi], bf[ni]);
    };

    const int NK = KTOT / BK;

    LDG_TILE(0);
    STS_A(0);
    STS_B(0);
    __syncthreads();

    #pragma unroll 1
    for (int kt = 0; kt < NK; ++kt) {
        const int s = kt & 1;
        const uint32_t sbase = sm32 + s * STAGE_BYTES;
        const bool more = (kt + 1 < NK);
        if (more) LDG_TILE(kt + 1);
        COMPUTE_KB(sbase, 0);
        COMPUTE_KB(sbase, 1);
        if (more) STS_A(s ^ 1);       // overlap writes under remaining MMAs
        COMPUTE_KB(sbase, 2);
        if (more) STS_B(s ^ 1);
        COMPUTE_KB(sbase, 3);
        __syncthreads();
    }

    // Epilogue: +bias, optional exact gelu, fp32 stores
    const float* bias = bias0 + (size_t)e * NTOT + bn;
    float* O = O0 + (size_t)grp * CCAP * NTOT + bn;

    #pragma unroll
    for (int mi = 0; mi < 4; ++mi) {
        const int r0 = bm + wr * 64 + mi * 16 + g;
        #pragma unroll
        for (int ni = 0; ni < 8; ++ni) {
            const int cc = wc * 64 + ni * 8 + tq * 2;
            const float2 bv = *reinterpret_cast<const float2*>(bias + cc);
            float v00 = acc[mi][ni][0] + bv.x;
            float v01 = acc[mi][ni][1] + bv.y;
            float v10 = acc[mi][ni][2] + bv.x;
            float v11 = acc[mi][ni][3] + bv.y;
            if (GELU) {
                v00 = gelu_exact(v00); v01 = gelu_exact(v01);
                v10 = gelu_exact(v10); v11 = gelu_exact(v11);
            }
            *reinterpret_cast<float2*>(O + (size_t)r0 * NTOT + cc)       = make_float2(v00, v01);
            *reinterpret_cast<float2*>(O + (size_t)(r0 + 8) * NTOT + cc) = make_float2(v10, v11);
        }
    }
}

extern "C" void kernel_launch(void* const* d_in, const int* in_sizes, int n_in,
                              void* d_out, int out_size)
{
    const float* inputs = (const float*)d_in[0];  // [4, 8192, 1024]
    const float* w1     = (const float*)d_in[1];  // [8, 4096, 1024]
    const float* b1     = (const float*)d_in[2];  // [8, 4096]
    const float* w2     = (const float*)d_in[3];  // [8, 1024, 4096]
    const float* b2     = (const float*)d_in[4];  // [8, 1024]
    float*       out    = (float*)d_out;          // [4, 8192, 1024]

    void* hptr = nullptr;
    cudaGetSymbolAddress(&hptr, g_h);
    float* h = (float*)hptr;

    cudaFuncSetAttribute(grouped_ffn<DFF, DMODEL, true>,
                         cudaFuncAttributeMaxDynamicSharedMemorySize, SMEM_BYTES);
    cudaFuncSetAttribute(grouped_ffn<DMODEL, DFF, false>,
                         cudaFuncAttributeMaxDynamicSharedMemorySize, SMEM_BYTES);

    // GEMM1 + gelu: h[grp][c][f]  (32 groups, M=1024, N=4096, K=1024)
    {
        dim3 grid(DFF / BN, CCAP / BM, BATCH * NUM_E);
        grouped_ffn<DFF, DMODEL, true><<<grid, 256, SMEM_BYTES>>>(inputs, w1, b1, h);
    }
    // GEMM2: out[grp][c][d]  (32 groups, M=1024, N=1024, K=4096)
    {
        dim3 grid(DMODEL / BN, CCAP / BM, BATCH * NUM_E);
        grouped_ffn<DMODEL, DFF, false><<<grid, 256, SMEM_BYTES>>>(h, w2, b2, out);
    }
}

// round 7
// speedup vs baseline: 1.4947x; 1.4947x over previous
#include <cuda_runtime.h>
#include <math.h>
#include <cstdint>

#define NUM_E   8
#define BATCH   4
#define CCAP    1024
#define DMODEL  1024
#define DFF     4096

// CTA tile 128x256, BK=32; 8 warps in 2x4 grid, each warp 64x64.
#define BM 128
#define BN 256
#define BK 32

// Row-major smem tiles, 32 words (128B) per row, XOR-swizzled 16B chunks:
//   chunk' = chunk ^ (row & 7)
#define A_TILE_BYTES (BM * BK * 4)                    // 16384
#define B_TILE_BYTES (BN * BK * 4)                    // 32768
#define STAGE_BYTES  (A_TILE_BYTES + B_TILE_BYTES)    // 49152
#define SMEM_BYTES   (2 * STAGE_BYTES + 128)

// 512 MB fp32 scratch for h = gelu(x@W1^T + b1)
__device__ float g_h[134217728];

__device__ __forceinline__ uint32_t smem_u32(const void* p) {
    uint32_t a;
    asm("{ .reg .u64 t; cvta.to.shared.u64 t, %1; cvt.u32.u64 %0, t; }" : "=r"(a) : "l"(p));
    return a;
}
__device__ __forceinline__ unsigned f2tf32(float x) {
    unsigned y;
    asm("cvt.rna.tf32.f32 %0, %1;" : "=r"(y) : "f"(x));
    return y;
}
__device__ __forceinline__ void sts128(uint32_t addr, uint4 v) {
    asm volatile("st.shared.v4.b32 [%0], {%1,%2,%3,%4};"
                 :: "r"(addr), "r"(v.x), "r"(v.y), "r"(v.z), "r"(v.w) : "memory");
}
__device__ __forceinline__ unsigned lds32(uint32_t addr) {
    unsigned v;
    asm volatile("ld.shared.b32 %0, [%1];" : "=r"(v) : "r"(addr));
    return v;
}
__device__ __forceinline__ void mma_tf32(float acc[4], const unsigned a[4], const unsigned b[2]) {
    asm volatile(
        "mma.sync.aligned.m16n8k8.row.col.f32.tf32.tf32.f32 "
        "{%0,%1,%2,%3}, {%4,%5,%6,%7}, {%8,%9}, {%0,%1,%2,%3};\n"
        : "+f"(acc[0]), "+f"(acc[1]), "+f"(acc[2]), "+f"(acc[3])
        : "r"(a[0]), "r"(a[1]), "r"(a[2]), "r"(a[3]),
          "r"(b[0]), "r"(b[1]));
}
__device__ __forceinline__ float gelu_exact(float x) {
    return 0.5f * x * (1.0f + erff(x * 0.7071067811865476f));
}

// Grouped NT GEMM: O[grp][m][n] = sum_k A[grp][m][k] * W[e][n][k] + bias[e][n] (opt gelu)
template<int NTOT, int KTOT, bool GELU>
__global__ void __launch_bounds__(256, 1)
grouped_ffn(const float* __restrict__ A0, const float* __restrict__ W0,
            const float* __restrict__ bias0, float* __restrict__ O0)
{
    extern __shared__ char smraw[];
    const uint32_t sm32 = (smem_u32(smraw) + 127u) & ~127u;

    const int tid  = threadIdx.x;
    const int wid  = tid >> 5;
    const int lane = tid & 31;
    const int wr   = wid >> 2;    // 0..1  (64-row slab)
    const int wc   = wid & 3;     // 0..3  (64-col slab)
    const int g    = lane >> 2;   // 0..7
    const int tq   = lane & 3;    // 0..3

    const int grp = blockIdx.z;
    const int e   = grp & (NUM_E - 1);
    const int bm  = blockIdx.y * BM;
    const int bn  = blockIdx.x * BN;

    const float* A = A0 + (size_t)grp * CCAP * KTOT + (size_t)bm * KTOT;
    const float* W = W0 + (size_t)e * NTOT * KTOT + (size_t)bn * KTOT;

    // ---- writer plan: thread t -> row (t>>3)+32i, 16B chunk (t&7) ----
    const int wrow = tid >> 3;    // 0..31
    const int wchk = tid & 7;     // 0..7
    const float* Ag = A + (size_t)wrow * KTOT + wchk * 4;
    const float* Wg = W + (size_t)wrow * KTOT + wchk * 4;

    // swizzled STS byte offsets within a tile (row&7 invariant under +32)
    uint32_t aso[4], bso[8];
    {
        const uint32_t sc = (uint32_t)(wchk ^ (wrow & 7)) << 4;
        #pragma unroll
        for (int i = 0; i < 4; ++i) aso[i] = (uint32_t)(wrow + 32 * i) * 128 + sc;
        #pragma unroll
        for (int i = 0; i < 8; ++i) bso[i] = (uint32_t)(wrow + 32 * i) * 128 + sc;
    }

    float4 ra[4], rb[8];
    auto LDG_TILE = [&](int kt) {
        const size_t k0 = (size_t)kt * BK;
        #pragma unroll
        for (int i = 0; i < 4; ++i)
            ra[i] = *reinterpret_cast<const float4*>(Ag + (size_t)(i * 32) * KTOT + k0);
        #pragma unroll
        for (int i = 0; i < 8; ++i)
            rb[i] = *reinterpret_cast<const float4*>(Wg + (size_t)(i * 32) * KTOT + k0);
    };
    auto STS_TILE = [&](int d) {
        const uint32_t abase = sm32 + d * STAGE_BYTES;
        #pragma unroll
        for (int i = 0; i < 4; ++i)
            sts128(abase + aso[i],
                   make_uint4(f2tf32(ra[i].x), f2tf32(ra[i].y), f2tf32(ra[i].z), f2tf32(ra[i].w)));
        const uint32_t bbase = abase + A_TILE_BYTES;
        #pragma unroll
        for (int i = 0; i < 8; ++i)
            sts128(bbase + bso[i],
                   make_uint4(f2tf32(rb[i].x), f2tf32(rb[i].y), f2tf32(rb[i].z), f2tf32(rb[i].w)));
    };

    // ---- scalar-LDS fragment plan ----
    // element (r,k): byte = r*128 + ((k>>2)^(r&7))*16 + (k&3)*4; here r&7 == g.
    // A rows: wr*64 + mi*16 + g (+8);  B rows: wc*64 + ni*8 + g.
    const uint32_t aRow0 = (uint32_t)(wr * 64 + g) * 128 + tq * 4;   // + mi*2048, +1024 for r+8
    const uint32_t bRow0 = (uint32_t)(wc * 64 + g) * 128 + tq * 4;   // + ni*1024
    uint32_t ck0[4];  // chunk byte offset for k-low half, per kb; k-high = ^16
    #pragma unroll
    for (int kb = 0; kb < 4; ++kb)
        ck0[kb] = (uint32_t)((2 * kb) ^ g) << 4;

    float acc[4][8][4];
    #pragma unroll
    for (int mi = 0; mi < 4; ++mi)
        #pragma unroll
        for (int ni = 0; ni < 8; ++ni)
            #pragma unroll
            for (int c = 0; c < 4; ++c)
                acc[mi][ni][c] = 0.0f;

    auto COMPUTE = [&](uint32_t sbase) {
        #pragma unroll
        for (int kb = 0; kb < 4; ++kb) {
            const uint32_t c0 = ck0[kb];
            unsigned af[4][4], bf[8][2];
            #pragma unroll
            for (int mi = 0; mi < 4; ++mi) {
                const uint32_t base = sbase + aRow0 + mi * 2048;
                af[mi][0] = lds32(base + c0);
                af[mi][1] = lds32(base + 1024 + c0);
                af[mi][2] = lds32(base + (c0 ^ 16));
                af[mi][3] = lds32(base + 1024 + (c0 ^ 16));
            }
            #pragma unroll
            for (int ni = 0; ni < 8; ++ni) {
                const uint32_t base = sbase + A_TILE_BYTES + bRow0 + ni * 1024;
                bf[ni][0] = lds32(base + c0);
                bf[ni][1] = lds32(base + (c0 ^ 16));
            }
            #pragma unroll
            for (int mi = 0; mi < 4; ++mi)
                #pragma unroll
                for (int ni = 0; ni < 8; ++ni)
                    mma_tf32(acc[mi][ni], af[mi], bf[ni]);
        }
    };

    const int NK = KTOT / BK;

    LDG_TILE(0);
    STS_TILE(0);
    __syncthreads();

    #pragma unroll 1
    for (int kt = 0; kt < NK; ++kt) {
        const int s = kt & 1;
        const bool more = (kt + 1 < NK);
        if (more) LDG_TILE(kt + 1);            // latency covered by full compute below
        COMPUTE(sm32 + s * STAGE_BYTES);
        if (more) STS_TILE(s ^ 1);             // s^1 free: all warps passed prior sync
        __syncthreads();
    }

    // Epilogue: +bias, optional exact gelu, fp32 stores
    const float* bias = bias0 + (size_t)e * NTOT + bn;
    float* O = O0 + (size_t)grp * CCAP * NTOT + bn;

    #pragma unroll
    for (int mi = 0; mi < 4; ++mi) {
        const int r0 = bm + wr * 64 + mi * 16 + g;
        #pragma unroll
        for (int ni = 0; ni < 8; ++ni) {
            const int cc = wc * 64 + ni * 8 + tq * 2;
            const float2 bv = *reinterpret_cast<const float2*>(bias + cc);
            float v00 = acc[mi][ni][0] + bv.x;
            float v01 = acc[mi][ni][1] + bv.y;
            float v10 = acc[mi][ni][2] + bv.x;
            float v11 = acc[mi][ni][3] + bv.y;
            if (GELU) {
                v00 = gelu_exact(v00); v01 = gelu_exact(v01);
                v10 = gelu_exact(v10); v11 = gelu_exact(v11);
            }
            *reinterpret_cast<float2*>(O + (size_t)r0 * NTOT + cc)       = make_float2(v00, v01);
            *reinterpret_cast<float2*>(O + (size_t)(r0 + 8) * NTOT + cc) = make_float2(v10, v11);
        }
    }
}

extern "C" void kernel_launch(void* const* d_in, const int* in_sizes, int n_in,
                              void* d_out, int out_size)
{
    const float* inputs = (const float*)d_in[0];  // [4, 8192, 1024]
    const float* w1     = (const float*)d_in[1];  // [8, 4096, 1024]
    const float* b1     = (const float*)d_in[2];  // [8, 4096]
    const float* w2     = (const float*)d_in[3];  // [8, 1024, 4096]
    const float* b2     = (const float*)d_in[4];  // [8, 1024]
    float*       out    = (float*)d_out;          // [4, 8192, 1024]

    void* hptr = nullptr;
    cudaGetSymbolAddress(&hptr, g_h);
    float* h = (float*)hptr;

    cudaFuncSetAttribute(grouped_ffn<DFF, DMODEL, true>,
                         cudaFuncAttributeMaxDynamicSharedMemorySize, SMEM_BYTES);
    cudaFuncSetAttribute(grouped_ffn<DMODEL, DFF, false>,
                         cudaFuncAttributeMaxDynamicSharedMemorySize, SMEM_BYTES);

    // GEMM1 + gelu: h[grp][c][f]  (32 groups, M=1024, N=4096, K=1024)
    {
        dim3 grid(DFF / BN, CCAP / BM, BATCH * NUM_E);
        grouped_ffn<DFF, DMODEL, true><<<grid, 256, SMEM_BYTES>>>(inputs, w1, b1, h);
    }
    // GEMM2: out[grp][c][d]  (32 groups, M=1024, N=1024, K=4096)
    {
        dim3 grid(DMODEL / BN, CCAP / BM, BATCH * NUM_E);
        grouped_ffn<DMODEL, DFF, false><<<grid, 256, SMEM_BYTES>>>(h, w2, b2, out);
    }
}